// round 7
// baseline (speedup 1.0000x reference)
#include <cuda_runtime.h>
#include <cuda_fp16.h>
#include <math_constants.h>
#include <mma.h>

using namespace nvcuda;

#define N_NODES 100000
#define E_EDGES 1600000
#define DIM 128
#define BM 128             // GEMM row tile
#define PADH 136           // smem row stride in halves (272B, 16B aligned)
#define PADF 132           // smem row stride in floats for C staging (528B)
#define NEG_SLOPE 0.01f
#define NB_SCAN 98         // ceil(100000/1024)
#define FULLM 0xffffffffu

// ---------------- device scratch (zero-initialized; g_cnt re-zeroed by agg) ----------------
__device__ __half g_h16[N_NODES * DIM];  // node features after linear (fp16, gather-only)
__device__ float  g_s[N_NODES];          // exp(leaky_relu(feat·w2)) per node
__device__ __half g_Wt16[DIM * DIM];     // Wt[k][o] = W[o][k]*mask[k], fp16
__device__ float  g_w2[DIM];             // mask ⊙ (W^T @ attn)
__device__ int    g_cnt[N_NODES];
__device__ int    g_off[N_NODES];
__device__ int    g_cur[N_NODES];
__device__ int    g_csrc[E_EDGES];
__device__ int    g_bsum[128];

// ---------------- count in-degrees ----------------
__global__ void count_kernel(const int* __restrict__ dst) {
    int e4 = blockIdx.x * blockDim.x + threadIdx.x;
    if (e4 < E_EDGES / 4) {
        int4 d = reinterpret_cast<const int4*>(dst)[e4];
        atomicAdd(&g_cnt[d.x], 1);
        atomicAdd(&g_cnt[d.y], 1);
        atomicAdd(&g_cnt[d.z], 1);
        atomicAdd(&g_cnt[d.w], 1);
    }
}

// ---------------- fold mask into W (transpose, fp16) + build w2 (fp32) ----------------
__global__ void prep_kernel(const float* __restrict__ W, const float* __restrict__ mask,
                            const float* __restrict__ attn) {
    int i = threadIdx.x;                 // k index 0..127
    float mi = mask[i];
    float acc = 0.f;
#pragma unroll 4
    for (int o = 0; o < DIM; ++o) {
        float w = W[o * DIM + i];        // coalesced over i
        g_Wt16[i * DIM + o] = __float2half_rn(w * mi);
        acc = fmaf(w, attn[o], acc);
    }
    g_w2[i] = mi * acc;
}

// ---------------- block-local exclusive scan ----------------
__global__ void scan1_kernel() {
    __shared__ int wsum[32];
    int idx  = blockIdx.x * 1024 + threadIdx.x;
    int lane = threadIdx.x & 31, wid = threadIdx.x >> 5;
    int v = (idx < N_NODES) ? g_cnt[idx] : 0;
    int inc = v;
#pragma unroll
    for (int d = 1; d < 32; d <<= 1) {
        int tmp = __shfl_up_sync(FULLM, inc, d);
        if (lane >= d) inc += tmp;
    }
    if (lane == 31) wsum[wid] = inc;
    __syncthreads();
    if (wid == 0) {
        int wv = wsum[lane];
        int winc = wv;
#pragma unroll
        for (int d = 1; d < 32; d <<= 1) {
            int tmp = __shfl_up_sync(FULLM, winc, d);
            if (lane >= d) winc += tmp;
        }
        wsum[lane] = winc - wv;
        if (lane == 31) g_bsum[blockIdx.x] = winc;
    }
    __syncthreads();
    if (idx < N_NODES) g_off[idx] = inc - v + wsum[wid];
}

// ---------------- fp16 wmma GEMM  h = feat @ Wt  (+ fused exp(leaky(score))) ----------------
__global__ void __launch_bounds__(256) gemm_kernel(const float* __restrict__ feat) {
    extern __shared__ __half smemh[];
    __half* As = smemh;                  // [128][PADH]
    __half* Bs = smemh + BM * PADH;      // [128][PADH]

    const int t    = threadIdx.x;
    const int lane = t & 31;
    const int wid  = t >> 5;
    const int wm   = wid & 3;            // 4 row groups of 32
    const int wn   = wid >> 2;           // 2 col groups of 64
    const int rb   = blockIdx.x * BM;

    // stage Wt16 -> Bs (uint4 = 8 halves)
    const uint4* wt8 = reinterpret_cast<const uint4*>(g_Wt16);
#pragma unroll
    for (int it = 0; it < 8; ++it) {
        int idx = t + it * 256;          // 0..2047
        int k = idx >> 4, q = idx & 15;
        *reinterpret_cast<uint4*>(&Bs[k * PADH + q * 8]) = wt8[k * 16 + q];
    }

    // stage feat -> As (fp16) + exact-fp32 score while values are in regs
    const float4* f4 = reinterpret_cast<const float4*>(feat);
    float4 w4 = reinterpret_cast<const float4*>(g_w2)[lane];
#pragma unroll
    for (int it = 0; it < 16; ++it) {
        int r = it * 8 + wid;
        int row = rb + r;
        float4 v = (row < N_NODES) ? f4[row * 32 + lane] : make_float4(0.f, 0.f, 0.f, 0.f);
        float p = v.x * w4.x + v.y * w4.y + v.z * w4.z + v.w * w4.w;
#pragma unroll
        for (int o = 16; o > 0; o >>= 1) p += __shfl_xor_sync(FULLM, p, o);
        if (lane == 0 && row < N_NODES) {
            float lr = (p > 0.f) ? p : NEG_SLOPE * p;
            g_s[row] = __expf(lr);       // pre-exponentiated score
        }
        __half2 lo = __floats2half2_rn(v.x, v.y);
        __half2 hi = __floats2half2_rn(v.z, v.w);
        uint2 u;
        u.x = *reinterpret_cast<unsigned*>(&lo);
        u.y = *reinterpret_cast<unsigned*>(&hi);
        *reinterpret_cast<uint2*>(&As[r * PADH + lane * 4]) = u;
    }
    __syncthreads();

    wmma::fragment<wmma::accumulator, 16, 16, 16, float> c[2][4];
#pragma unroll
    for (int i = 0; i < 2; ++i)
#pragma unroll
        for (int j = 0; j < 4; ++j) wmma::fill_fragment(c[i][j], 0.f);

#pragma unroll
    for (int k0 = 0; k0 < DIM; k0 += 16) {
        wmma::fragment<wmma::matrix_a, 16, 16, 16, __half, wmma::row_major> a[2];
        wmma::fragment<wmma::matrix_b, 16, 16, 16, __half, wmma::row_major> b[4];
#pragma unroll
        for (int i = 0; i < 2; ++i)
            wmma::load_matrix_sync(a[i], &As[(wm * 32 + i * 16) * PADH + k0], PADH);
#pragma unroll
        for (int j = 0; j < 4; ++j)
            wmma::load_matrix_sync(b[j], &Bs[k0 * PADH + wn * 64 + j * 16], PADH);
#pragma unroll
        for (int i = 0; i < 2; ++i)
#pragma unroll
            for (int j = 0; j < 4; ++j)
                wmma::mma_sync(c[i][j], a[i], b[j], c[i][j]);
    }

    __syncthreads();
    float* Cs = reinterpret_cast<float*>(smemh);   // [128][PADF]
#pragma unroll
    for (int i = 0; i < 2; ++i)
#pragma unroll
        for (int j = 0; j < 4; ++j)
            wmma::store_matrix_sync(&Cs[(wm * 32 + i * 16) * PADF + wn * 64 + j * 16],
                                    c[i][j], PADF, wmma::mem_row_major);
    __syncthreads();
    uint2* h16 = reinterpret_cast<uint2*>(g_h16);
#pragma unroll
    for (int it = 0; it < 16; ++it) {
        int idx = t + it * 256;
        int r = idx >> 5, kq = idx & 31;
        int row = rb + r;
        if (row < N_NODES) {
            float4 v = *reinterpret_cast<float4*>(&Cs[r * PADF + kq * 4]);
            __half2 lo = __floats2half2_rn(v.x, v.y);
            __half2 hi = __floats2half2_rn(v.z, v.w);
            uint2 u;
            u.x = *reinterpret_cast<unsigned*>(&lo);
            u.y = *reinterpret_cast<unsigned*>(&hi);
            h16[row * 32 + kq] = u;
        }
    }
}

// ---------------- scan block sums ----------------
__global__ void scan2_kernel() {
    __shared__ int sm[128];
    int t = threadIdx.x;
    int v = (t < NB_SCAN) ? g_bsum[t] : 0;
    sm[t] = v;
    __syncthreads();
#pragma unroll
    for (int d = 1; d < 128; d <<= 1) {
        int add = (t >= d) ? sm[t - d] : 0;
        __syncthreads();
        sm[t] += add;
        __syncthreads();
    }
    if (t < NB_SCAN) g_bsum[t] = sm[t] - v;
}

// ---------------- add block offsets; init fill cursors ----------------
__global__ void scan3_kernel() {
    int idx = blockIdx.x * blockDim.x + threadIdx.x;
    if (idx < N_NODES) {
        int o = g_off[idx] + g_bsum[idx >> 10];
        g_off[idx] = o;
        g_cur[idx] = o;
    }
}

// ---------------- scatter edges into CSR buckets ----------------
__global__ void fill_kernel(const int* __restrict__ src, const int* __restrict__ dst) {
    int e4 = blockIdx.x * blockDim.x + threadIdx.x;
    if (e4 < E_EDGES / 4) {
        int4 s = reinterpret_cast<const int4*>(src)[e4];
        int4 d = reinterpret_cast<const int4*>(dst)[e4];
        g_csrc[atomicAdd(&g_cur[d.x], 1)] = s.x;
        g_csrc[atomicAdd(&g_cur[d.y], 1)] = s.y;
        g_csrc[atomicAdd(&g_cur[d.z], 1)] = s.z;
        g_csrc[atomicAdd(&g_cur[d.w], 1)] = s.w;
    }
}

// ---------------- per-dst aggregation: warp-batched indices + shfl broadcast ----------------
// One warp per dst node. Per 32-edge chunk: 1 coalesced csrc load + 1 s-gather load,
// then indices/weights distributed via shfl; h-row loads run 8-deep independent.
__global__ void __launch_bounds__(256) agg_kernel(float* __restrict__ out) {
    int gtid = blockIdx.x * blockDim.x + threadIdx.x;
    int v    = gtid >> 5;
    int lane = gtid & 31;
    if (v >= N_NODES) return;

    int n   = g_cnt[v];
    int beg = g_off[v];
    float4 acc = make_float4(0.f, 0.f, 0.f, 0.f);
    float denom = 0.f;
    const uint2* hp = reinterpret_cast<const uint2*>(g_h16);

    for (int base = 0; base < n; base += 32) {
        int cnt = min(n - base, 32);
        int idx = 0; float w = 0.f;
        if (lane < cnt) {
            idx = g_csrc[beg + base + lane];   // one coalesced load per chunk
            w   = g_s[idx];                    // one gather per chunk (pre-exp'd)
        }
        // denom from warp reduction
        float dsum = w;
#pragma unroll
        for (int o = 16; o > 0; o >>= 1) dsum += __shfl_xor_sync(FULLM, dsum, o);
        denom += dsum;

        int j = 0;
        for (; j + 8 <= cnt; j += 8) {
#pragma unroll
            for (int q = 0; q < 8; ++q) {
                int   iq = __shfl_sync(FULLM, idx, j + q);
                float wq = __shfl_sync(FULLM, w,   j + q);
                uint2 u  = hp[iq * 32 + lane];
                float2 A = __half22float2(*reinterpret_cast<__half2*>(&u.x));
                float2 B = __half22float2(*reinterpret_cast<__half2*>(&u.y));
                acc.x += wq * A.x; acc.y += wq * A.y;
                acc.z += wq * B.x; acc.w += wq * B.y;
            }
        }
        for (; j < cnt; ++j) {
            int   iq = __shfl_sync(FULLM, idx, j);
            float wq = __shfl_sync(FULLM, w,   j);
            uint2 u  = hp[iq * 32 + lane];
            float2 A = __half22float2(*reinterpret_cast<__half2*>(&u.x));
            float2 B = __half22float2(*reinterpret_cast<__half2*>(&u.y));
            acc.x += wq * A.x; acc.y += wq * A.y;
            acc.z += wq * B.x; acc.w += wq * B.y;
        }
    }

    if (n > 0) {
        float inv = 1.f / denom;
        acc.x *= inv; acc.y *= inv; acc.z *= inv; acc.w *= inv;
        if (lane == 0) g_cnt[v] = 0;   // reset for next replay
    }
    acc.x = fmaxf(acc.x, 0.f); acc.y = fmaxf(acc.y, 0.f);
    acc.z = fmaxf(acc.z, 0.f); acc.w = fmaxf(acc.w, 0.f);
    reinterpret_cast<float4*>(out)[v * 32 + lane] = acc;
}

// ---------------- launch (gemm kept at index 3 for ncu) ----------------
extern "C" void kernel_launch(void* const* d_in, const int* in_sizes, int n_in,
                              void* d_out, int out_size) {
    const float* feat = (const float*)d_in[0];
    const float* mask = (const float*)d_in[1];
    const float* W    = (const float*)d_in[2];
    const float* attn = (const float*)d_in[3];
    const int*   src  = (const int*)d_in[4];
    const int*   dst  = (const int*)d_in[5];
    float* out = (float*)d_out;

    count_kernel<<<(E_EDGES / 4 + 255) / 256, 256>>>(dst);        // 0
    prep_kernel<<<1, 128>>>(W, mask, attn);                       // 1
    scan1_kernel<<<NB_SCAN, 1024>>>();                            // 2

    const int smemB = 2 * BM * PADH * (int)sizeof(__half);        // 69,632 B
    cudaFuncSetAttribute(gemm_kernel, cudaFuncAttributeMaxDynamicSharedMemorySize, smemB);
    gemm_kernel<<<(N_NODES + BM - 1) / BM, 256, smemB>>>(feat);   // 3  <-- profiled

    scan2_kernel<<<1, 128>>>();                                   // 4
    scan3_kernel<<<(N_NODES + 255) / 256, 256>>>();               // 5
    fill_kernel<<<(E_EDGES / 4 + 255) / 256, 256>>>(src, dst);    // 6
    agg_kernel<<<(N_NODES * 32 + 255) / 256, 256>>>(out);         // 7
}

// round 8
// speedup vs baseline: 1.1210x; 1.1210x over previous
#include <cuda_runtime.h>
#include <cuda_fp16.h>
#include <math_constants.h>
#include <mma.h>

using namespace nvcuda;

#define N_NODES 100000
#define E_EDGES 1600000
#define DIM 128
#define BM 128             // GEMM row tile
#define PADH 136           // smem row stride in halves (272B, 16B aligned)
#define PADF 132           // smem row stride in floats for C staging (528B)
#define NEG_SLOPE 0.01f
#define FULLM 0xffffffffu

// ---------------- device scratch (zero-initialized; g_cnt re-zeroed by agg) ----------------
__device__ __half g_h16[N_NODES * DIM];  // node features after linear (fp16, gather-only)
__device__ float  g_s[N_NODES];          // exp(leaky_relu(feat·w2)) per node
__device__ float  g_w2[DIM];             // mask ⊙ (W^T @ attn)
__device__ __half g_Wt16[DIM * DIM];     // Wt[k][o] = W[o][k]*mask[k], fp16
__device__ int    g_cnt[N_NODES];
__device__ int    g_off[N_NODES];
__device__ int    g_cur[N_NODES];
__device__ int    g_csrc[E_EDGES];
__device__ int    g_total;               // global CSR cursor

// ---------------- CSR chain K0: count in-degrees (+reset global cursor) ----------------
__global__ void count_kernel(const int* __restrict__ dst) {
    int e4 = blockIdx.x * blockDim.x + threadIdx.x;
    if (e4 == 0) g_total = 0;            // visible to assign (same-stream successor)
    if (e4 < E_EDGES / 4) {
        int4 d = reinterpret_cast<const int4*>(dst)[e4];
        atomicAdd(&g_cnt[d.x], 1);
        atomicAdd(&g_cnt[d.y], 1);
        atomicAdd(&g_cnt[d.z], 1);
        atomicAdd(&g_cnt[d.w], 1);
    }
}

// ---------------- CSR chain K1: order-free bucket assignment (replaces 3 scan kernels) ----
__global__ void assign_kernel() {
    int idx = blockIdx.x * blockDim.x + threadIdx.x;
    if (idx < N_NODES) {
        int c = g_cnt[idx];
        int o = (c > 0) ? atomicAdd(&g_total, c) : 0;
        g_off[idx] = o;
        g_cur[idx] = o;
    }
}

// ---------------- CSR chain K2: scatter edges into buckets ----------------
__global__ void fill_kernel(const int* __restrict__ src, const int* __restrict__ dst) {
    int e4 = blockIdx.x * blockDim.x + threadIdx.x;
    if (e4 < E_EDGES / 4) {
        int4 s = reinterpret_cast<const int4*>(src)[e4];
        int4 d = reinterpret_cast<const int4*>(dst)[e4];
        g_csrc[atomicAdd(&g_cur[d.x], 1)] = s.x;
        g_csrc[atomicAdd(&g_cur[d.y], 1)] = s.y;
        g_csrc[atomicAdd(&g_cur[d.z], 1)] = s.z;
        g_csrc[atomicAdd(&g_cur[d.w], 1)] = s.w;
    }
}

// ---------------- GEMM chain K0: fold mask into W (fp16) + build w2 ----------------
__global__ void prep_kernel(const float* __restrict__ W, const float* __restrict__ mask,
                            const float* __restrict__ attn) {
    int i = threadIdx.x;                 // k index 0..127
    float mi = mask[i];
    float acc = 0.f;
#pragma unroll 4
    for (int o = 0; o < DIM; ++o) {
        float w = W[o * DIM + i];        // coalesced over i
        g_Wt16[i * DIM + o] = __float2half_rn(w * mi);
        acc = fmaf(w, attn[o], acc);
    }
    g_w2[i] = mi * acc;
}

// ---------------- GEMM chain K1: fp16 wmma  h = feat @ Wt  (+ fused exp(leaky(score))) ----
__global__ void __launch_bounds__(256) gemm_kernel(const float* __restrict__ feat) {
    extern __shared__ __half smemh[];
    __half* As = smemh;                  // [128][PADH]
    __half* Bs = smemh + BM * PADH;      // [128][PADH]

    const int t    = threadIdx.x;
    const int lane = t & 31;
    const int wid  = t >> 5;
    const int wm   = wid & 3;            // 4 row groups of 32
    const int wn   = wid >> 2;           // 2 col groups of 64
    const int rb   = blockIdx.x * BM;

    // stage Wt16 -> Bs (uint4 = 8 halves)
    const uint4* wt8 = reinterpret_cast<const uint4*>(g_Wt16);
#pragma unroll
    for (int it = 0; it < 8; ++it) {
        int idx = t + it * 256;          // 0..2047
        int k = idx >> 4, q = idx & 15;
        *reinterpret_cast<uint4*>(&Bs[k * PADH + q * 8]) = wt8[k * 16 + q];
    }

    // stage feat -> As (fp16) + exact-fp32 score while values are in regs
    const float4* f4 = reinterpret_cast<const float4*>(feat);
    float4 w4 = reinterpret_cast<const float4*>(g_w2)[lane];
#pragma unroll
    for (int it = 0; it < 16; ++it) {
        int r = it * 8 + wid;
        int row = rb + r;
        float4 v = (row < N_NODES) ? f4[row * 32 + lane] : make_float4(0.f, 0.f, 0.f, 0.f);
        float p = v.x * w4.x + v.y * w4.y + v.z * w4.z + v.w * w4.w;
#pragma unroll
        for (int o = 16; o > 0; o >>= 1) p += __shfl_xor_sync(FULLM, p, o);
        if (lane == 0 && row < N_NODES) {
            float lr = (p > 0.f) ? p : NEG_SLOPE * p;
            g_s[row] = __expf(lr);       // pre-exponentiated score
        }
        __half2 lo = __floats2half2_rn(v.x, v.y);
        __half2 hi = __floats2half2_rn(v.z, v.w);
        uint2 u;
        u.x = *reinterpret_cast<unsigned*>(&lo);
        u.y = *reinterpret_cast<unsigned*>(&hi);
        *reinterpret_cast<uint2*>(&As[r * PADH + lane * 4]) = u;
    }
    __syncthreads();

    wmma::fragment<wmma::accumulator, 16, 16, 16, float> c[2][4];
#pragma unroll
    for (int i = 0; i < 2; ++i)
#pragma unroll
        for (int j = 0; j < 4; ++j) wmma::fill_fragment(c[i][j], 0.f);

#pragma unroll
    for (int k0 = 0; k0 < DIM; k0 += 16) {
        wmma::fragment<wmma::matrix_a, 16, 16, 16, __half, wmma::row_major> a[2];
        wmma::fragment<wmma::matrix_b, 16, 16, 16, __half, wmma::row_major> b[4];
#pragma unroll
        for (int i = 0; i < 2; ++i)
            wmma::load_matrix_sync(a[i], &As[(wm * 32 + i * 16) * PADH + k0], PADH);
#pragma unroll
        for (int j = 0; j < 4; ++j)
            wmma::load_matrix_sync(b[j], &Bs[k0 * PADH + wn * 64 + j * 16], PADH);
#pragma unroll
        for (int i = 0; i < 2; ++i)
#pragma unroll
            for (int j = 0; j < 4; ++j)
                wmma::mma_sync(c[i][j], a[i], b[j], c[i][j]);
    }

    __syncthreads();
    float* Cs = reinterpret_cast<float*>(smemh);   // [128][PADF]
#pragma unroll
    for (int i = 0; i < 2; ++i)
#pragma unroll
        for (int j = 0; j < 4; ++j)
            wmma::store_matrix_sync(&Cs[(wm * 32 + i * 16) * PADF + wn * 64 + j * 16],
                                    c[i][j], PADF, wmma::mem_row_major);
    __syncthreads();
    uint2* h16 = reinterpret_cast<uint2*>(g_h16);
#pragma unroll
    for (int it = 0; it < 16; ++it) {
        int idx = t + it * 256;
        int r = idx >> 5, kq = idx & 31;
        int row = rb + r;
        if (row < N_NODES) {
            float4 v = *reinterpret_cast<float4*>(&Cs[r * PADF + kq * 4]);
            __half2 lo = __floats2half2_rn(v.x, v.y);
            __half2 hi = __floats2half2_rn(v.z, v.w);
            uint2 u;
            u.x = *reinterpret_cast<unsigned*>(&lo);
            u.y = *reinterpret_cast<unsigned*>(&hi);
            h16[row * 32 + kq] = u;
        }
    }
}

// ---------------- join K: per-dst aggregation (warp-batched, fp16 gather) ----------------
__global__ void __launch_bounds__(256) agg_kernel(float* __restrict__ out) {
    int gtid = blockIdx.x * blockDim.x + threadIdx.x;
    int v    = gtid >> 5;
    int lane = gtid & 31;
    if (v >= N_NODES) return;

    int n   = g_cnt[v];
    int beg = g_off[v];
    float4 acc = make_float4(0.f, 0.f, 0.f, 0.f);
    float denom = 0.f;
    const uint2* hp = reinterpret_cast<const uint2*>(g_h16);

    for (int base = 0; base < n; base += 32) {
        int cnt = min(n - base, 32);
        int idx = 0; float w = 0.f;
        if (lane < cnt) {
            idx = g_csrc[beg + base + lane];   // one coalesced load per chunk
            w   = g_s[idx];                    // one gather per chunk (pre-exp'd)
        }
        float dsum = w;
#pragma unroll
        for (int o = 16; o > 0; o >>= 1) dsum += __shfl_xor_sync(FULLM, dsum, o);
        denom += dsum;

        int j = 0;
        for (; j + 8 <= cnt; j += 8) {
#pragma unroll
            for (int q = 0; q < 8; ++q) {
                int   iq = __shfl_sync(FULLM, idx, j + q);
                float wq = __shfl_sync(FULLM, w,   j + q);
                uint2 u  = hp[iq * 32 + lane];
                float2 A = __half22float2(*reinterpret_cast<__half2*>(&u.x));
                float2 B = __half22float2(*reinterpret_cast<__half2*>(&u.y));
                acc.x += wq * A.x; acc.y += wq * A.y;
                acc.z += wq * B.x; acc.w += wq * B.y;
            }
        }
        for (; j < cnt; ++j) {
            int   iq = __shfl_sync(FULLM, idx, j);
            float wq = __shfl_sync(FULLM, w,   j);
            uint2 u  = hp[iq * 32 + lane];
            float2 A = __half22float2(*reinterpret_cast<__half2*>(&u.x));
            float2 B = __half22float2(*reinterpret_cast<__half2*>(&u.y));
            acc.x += wq * A.x; acc.y += wq * A.y;
            acc.z += wq * B.x; acc.w += wq * B.y;
        }
    }

    if (n > 0) {
        float inv = 1.f / denom;
        acc.x *= inv; acc.y *= inv; acc.z *= inv; acc.w *= inv;
        if (lane == 0) g_cnt[v] = 0;   // reset for next replay
    }
    acc.x = fmaxf(acc.x, 0.f); acc.y = fmaxf(acc.y, 0.f);
    acc.z = fmaxf(acc.z, 0.f); acc.w = fmaxf(acc.w, 0.f);
    reinterpret_cast<float4*>(out)[v * 32 + lane] = acc;
}

// ---------------- launch: fork-join — GEMM chain ∥ CSR chain, join at agg ----------------
extern "C" void kernel_launch(void* const* d_in, const int* in_sizes, int n_in,
                              void* d_out, int out_size) {
    const float* feat = (const float*)d_in[0];
    const float* mask = (const float*)d_in[1];
    const float* W    = (const float*)d_in[2];
    const float* attn = (const float*)d_in[3];
    const int*   src  = (const int*)d_in[4];
    const int*   dst  = (const int*)d_in[5];
    float* out = (float*)d_out;

    // fresh side-stream + events each call (host objects only; no device allocation).
    cudaStream_t side;
    cudaStreamCreateWithFlags(&side, cudaStreamNonBlocking);
    cudaEvent_t eFork, eJoin;
    cudaEventCreateWithFlags(&eFork, cudaEventDisableTiming);
    cudaEventCreateWithFlags(&eJoin, cudaEventDisableTiming);

    // fork: side stream branches off the (captured) base stream
    cudaEventRecord(eFork, 0);
    cudaStreamWaitEvent(side, eFork, 0);

    // GEMM chain on side stream
    prep_kernel<<<1, 128, 0, side>>>(W, mask, attn);
    const int smemB = 2 * BM * PADH * (int)sizeof(__half);        // 69,632 B
    cudaFuncSetAttribute(gemm_kernel, cudaFuncAttributeMaxDynamicSharedMemorySize, smemB);
    gemm_kernel<<<(N_NODES + BM - 1) / BM, 256, smemB, side>>>(feat);
    cudaEventRecord(eJoin, side);

    // CSR chain on base stream (runs concurrently with GEMM chain)
    count_kernel<<<(E_EDGES / 4 + 255) / 256, 256>>>(dst);
    assign_kernel<<<(N_NODES + 255) / 256, 256>>>();
    fill_kernel<<<(E_EDGES / 4 + 255) / 256, 256>>>(src, dst);

    // join: agg needs both chains
    cudaStreamWaitEvent(0, eJoin, 0);
    agg_kernel<<<(N_NODES * 32 + 255) / 256, 256>>>(out);
}